// round 1
// baseline (speedup 1.0000x reference)
#include <cuda_runtime.h>
#include <math.h>

#define T_TOK 2048
#define NE 8
#define TOPK 2
#define HD 2048
#define ID 1408
#define ISD 5632

// ---------------- scratch (static device globals; no allocation) -------------
__device__ float d_Hs[(size_t)T_TOK * ISD];          // shared expert hidden (silu(g)*u)
__device__ float d_Hr[(size_t)NE * T_TOK * ID];      // routed hidden, per-expert regions
__device__ float d_Y [(size_t)NE * T_TOK * HD];      // routed down output (weight-scaled)
__device__ int   d_tok[NE * T_TOK];                  // per-expert gathered token ids
__device__ float d_wt [NE * T_TOK];                  // per-expert row combine weights
__device__ int   d_cnt[NE];                          // per-expert row counts
__device__ int   d_slot[T_TOK * TOPK];               // token -> row slot in d_Y
__device__ int   d_topki[T_TOK * TOPK];
__device__ float d_topkw[T_TOK * TOPK];

// ---------------- routing: logits -> softmax -> top2 -> renorm ---------------
__global__ void route_kernel(const float* __restrict__ x, const float* __restrict__ gw)
{
    int warp = (blockIdx.x * blockDim.x + threadIdx.x) >> 5;
    int lane = threadIdx.x & 31;
    if (warp >= T_TOK) return;
    const float* xr = x + (size_t)warp * HD;

    float s[NE];
#pragma unroll
    for (int e = 0; e < NE; e++) s[e] = 0.f;
    for (int k = lane; k < HD; k += 32) {
        float xv = xr[k];
#pragma unroll
        for (int e = 0; e < NE; e++) s[e] += xv * gw[e * HD + k];
    }
#pragma unroll
    for (int e = 0; e < NE; e++)
#pragma unroll
        for (int off = 16; off; off >>= 1)
            s[e] += __shfl_down_sync(0xffffffffu, s[e], off);

    if (lane == 0) {
        float mx = s[0];
#pragma unroll
        for (int e = 1; e < NE; e++) mx = fmaxf(mx, s[e]);
        float g[NE], sum = 0.f;
#pragma unroll
        for (int e = 0; e < NE; e++) { g[e] = expf(s[e] - mx); sum += g[e]; }
        float inv = 1.f / sum;
#pragma unroll
        for (int e = 0; e < NE; e++) g[e] *= inv;
        // top-2, lowest index wins ties (matches jax top_k)
        int i0 = 0; float v0 = g[0];
#pragma unroll
        for (int e = 1; e < NE; e++) if (g[e] > v0) { v0 = g[e]; i0 = e; }
        int i1 = -1; float v1 = -1.f;
#pragma unroll
        for (int e = 0; e < NE; e++) if (e != i0 && g[e] > v1) { v1 = g[e]; i1 = e; }
        float dn = 1.f / (v0 + v1);
        d_topki[warp * 2 + 0] = i0;  d_topkw[warp * 2 + 0] = v0 * dn;
        d_topki[warp * 2 + 1] = i1;  d_topkw[warp * 2 + 1] = v1 * dn;
    }
}

// -------- deterministic per-expert compaction (block scan, 8 blocks) ---------
__global__ void build_kernel()
{
    int e = blockIdx.x;
    int tid = threadIdx.x;
    int lane = tid & 31, w = tid >> 5;
    __shared__ int warp_sums[8];
    __shared__ int s_base;
    if (tid == 0) s_base = 0;
    __syncthreads();

    for (int c = 0; c < T_TOK; c += 256) {
        int t = c + tid;
        int k = -1;
        if (d_topki[2 * t] == e) k = 0;
        else if (d_topki[2 * t + 1] == e) k = 1;
        int flag = (k >= 0) ? 1 : 0;
        unsigned bal = __ballot_sync(0xffffffffu, flag);
        int pre = __popc(bal & ((1u << lane) - 1u));
        if (lane == 31) warp_sums[w] = pre + flag;
        __syncthreads();
        int wbase = 0;
        for (int i = 0; i < w; i++) wbase += warp_sums[i];
        int pos = s_base + wbase + pre;
        if (flag) {
            d_tok [e * T_TOK + pos] = t;
            d_wt  [e * T_TOK + pos] = d_topkw[2 * t + k];
            d_slot[2 * t + k]       = e * T_TOK + pos;
        }
        __syncthreads();
        if (tid == 0) {
            int tot = 0;
            for (int i = 0; i < 8; i++) tot += warp_sums[i];
            s_base += tot;
        }
        __syncthreads();
    }
    if (tid == 0) d_cnt[e] = s_base;
}

// -------- fused gate+up SGEMM with SiLU(g)*u epilogue -------------------------
// C[m][n] = silu(A·Bg^T) * (A·Bu^T), A rows optionally gathered (EXPERT)
template <bool EXPERT>
__global__ __launch_bounds__(256)
void swiglu_gemm_k(const float* __restrict__ A,
                   const float* __restrict__ Bg_all,
                   const float* __restrict__ Bu_all,
                   int N, int Kd)
{
    const int z = EXPERT ? blockIdx.z : 0;
    const float* Bg = Bg_all + (size_t)z * N * Kd;
    const float* Bu = Bu_all + (size_t)z * N * Kd;
    float* C = EXPERT ? (d_Hr + (size_t)z * T_TOK * N) : d_Hs;
    const int M = EXPERT ? d_cnt[z] : T_TOK;

    int row0 = blockIdx.y * 64;
    if (row0 >= M) return;
    int col0 = blockIdx.x * 64;

    __shared__ float As [16][68];
    __shared__ float Bgs[16][68];
    __shared__ float Bus[16][68];

    int tid = threadIdx.x;
    int lr  = tid >> 2;        // 0..63
    int lk4 = (tid & 3) * 4;   // 0,4,8,12

    int ar = row0 + lr;
    bool avalid = ar < M;
    int grow = avalid ? (EXPERT ? d_tok[z * T_TOK + ar] : ar) : 0;
    const float* Arow  = A  + (size_t)grow * Kd;
    const float* Bgrow = Bg + (size_t)(col0 + lr) * Kd;
    const float* Burow = Bu + (size_t)(col0 + lr) * Kd;

    int tx = tid & 15, ty = tid >> 4;
    float accg[4][4], accu[4][4];
#pragma unroll
    for (int i = 0; i < 4; i++)
#pragma unroll
        for (int j = 0; j < 4; j++) { accg[i][j] = 0.f; accu[i][j] = 0.f; }

    for (int k0 = 0; k0 < Kd; k0 += 16) {
        float4 av = avalid ? *(const float4*)(Arow + k0 + lk4)
                           : make_float4(0.f, 0.f, 0.f, 0.f);
        float4 bg = *(const float4*)(Bgrow + k0 + lk4);
        float4 bu = *(const float4*)(Burow + k0 + lk4);
        As [lk4 + 0][lr] = av.x; As [lk4 + 1][lr] = av.y; As [lk4 + 2][lr] = av.z; As [lk4 + 3][lr] = av.w;
        Bgs[lk4 + 0][lr] = bg.x; Bgs[lk4 + 1][lr] = bg.y; Bgs[lk4 + 2][lr] = bg.z; Bgs[lk4 + 3][lr] = bg.w;
        Bus[lk4 + 0][lr] = bu.x; Bus[lk4 + 1][lr] = bu.y; Bus[lk4 + 2][lr] = bu.z; Bus[lk4 + 3][lr] = bu.w;
        __syncthreads();
#pragma unroll
        for (int k = 0; k < 16; k++) {
            float a[4], bgr[4], bur[4];
#pragma unroll
            for (int i = 0; i < 4; i++) a[i] = As[k][ty * 4 + i];
#pragma unroll
            for (int j = 0; j < 4; j++) { bgr[j] = Bgs[k][tx * 4 + j]; bur[j] = Bus[k][tx * 4 + j]; }
#pragma unroll
            for (int i = 0; i < 4; i++)
#pragma unroll
                for (int j = 0; j < 4; j++) {
                    accg[i][j] += a[i] * bgr[j];
                    accu[i][j] += a[i] * bur[j];
                }
        }
        __syncthreads();
    }

#pragma unroll
    for (int i = 0; i < 4; i++) {
        int m = row0 + ty * 4 + i;
        if (m < M) {
            float v[4];
#pragma unroll
            for (int j = 0; j < 4; j++) {
                float g = accg[i][j];
                v[j] = g / (1.f + expf(-g)) * accu[i][j];
            }
            *(float4*)(C + (size_t)m * N + col0 + tx * 4) = make_float4(v[0], v[1], v[2], v[3]);
        }
    }
}

// -------- down-proj SGEMM, optional per-row combine weight in epilogue --------
template <bool EXPERT>
__global__ __launch_bounds__(256)
void down_gemm_k(const float* __restrict__ B_all, float* __restrict__ Cout,
                 int N, int Kd)
{
    const int z = EXPERT ? blockIdx.z : 0;
    const float* A = EXPERT ? (d_Hr + (size_t)z * T_TOK * Kd) : d_Hs;
    const float* B = B_all + (size_t)z * N * Kd;
    float* C = EXPERT ? (d_Y + (size_t)z * T_TOK * N) : Cout;
    const int M = EXPERT ? d_cnt[z] : T_TOK;

    int row0 = blockIdx.y * 64;
    if (row0 >= M) return;
    int col0 = blockIdx.x * 64;

    __shared__ float As[16][68];
    __shared__ float Bs[16][68];

    int tid = threadIdx.x;
    int lr  = tid >> 2;
    int lk4 = (tid & 3) * 4;

    int ar = row0 + lr;
    bool avalid = ar < M;
    const float* Arow = A + (size_t)(avalid ? ar : 0) * Kd;
    const float* Brow = B + (size_t)(col0 + lr) * Kd;

    int tx = tid & 15, ty = tid >> 4;
    float acc[4][4];
#pragma unroll
    for (int i = 0; i < 4; i++)
#pragma unroll
        for (int j = 0; j < 4; j++) acc[i][j] = 0.f;

    for (int k0 = 0; k0 < Kd; k0 += 16) {
        float4 av = avalid ? *(const float4*)(Arow + k0 + lk4)
                           : make_float4(0.f, 0.f, 0.f, 0.f);
        float4 bv = *(const float4*)(Brow + k0 + lk4);
        As[lk4 + 0][lr] = av.x; As[lk4 + 1][lr] = av.y; As[lk4 + 2][lr] = av.z; As[lk4 + 3][lr] = av.w;
        Bs[lk4 + 0][lr] = bv.x; Bs[lk4 + 1][lr] = bv.y; Bs[lk4 + 2][lr] = bv.z; Bs[lk4 + 3][lr] = bv.w;
        __syncthreads();
#pragma unroll
        for (int k = 0; k < 16; k++) {
            float a[4], b[4];
#pragma unroll
            for (int i = 0; i < 4; i++) a[i] = As[k][ty * 4 + i];
#pragma unroll
            for (int j = 0; j < 4; j++) b[j] = Bs[k][tx * 4 + j];
#pragma unroll
            for (int i = 0; i < 4; i++)
#pragma unroll
                for (int j = 0; j < 4; j++) acc[i][j] += a[i] * b[j];
        }
        __syncthreads();
    }

#pragma unroll
    for (int i = 0; i < 4; i++) {
        int m = row0 + ty * 4 + i;
        if (m < M) {
            float s = EXPERT ? d_wt[z * T_TOK + m] : 1.f;
            *(float4*)(C + (size_t)m * N + col0 + tx * 4) =
                make_float4(acc[i][0] * s, acc[i][1] * s, acc[i][2] * s, acc[i][3] * s);
        }
    }
}

// -------- final combine: out += Y[slot0] + Y[slot1] (weights already folded) --
__global__ void combine_kernel(float* __restrict__ out)
{
    int idx = blockIdx.x * blockDim.x + threadIdx.x;     // over T*H/4
    int t  = idx / (HD / 4);
    int h4 = idx % (HD / 4);
    int s0 = d_slot[2 * t], s1 = d_slot[2 * t + 1];
    float4 o = ((float4*)out)[idx];
    float4 a = ((const float4*)(d_Y + (size_t)s0 * HD))[h4];
    float4 b = ((const float4*)(d_Y + (size_t)s1 * HD))[h4];
    o.x += a.x + b.x;  o.y += a.y + b.y;  o.z += a.z + b.z;  o.w += a.w + b.w;
    ((float4*)out)[idx] = o;
}

// ---------------- launcher ---------------------------------------------------
extern "C" void kernel_launch(void* const* d_in, const int* in_sizes, int n_in,
                              void* d_out, int out_size)
{
    const float* x   = (const float*)d_in[0];  // [B,S,H] = [T_TOK, HD]
    const float* gw  = (const float*)d_in[1];  // [E, H]
    const float* egw = (const float*)d_in[2];  // [E, I, H]
    const float* euw = (const float*)d_in[3];  // [E, I, H]
    const float* edw = (const float*)d_in[4];  // [E, H, I]
    const float* sgw = (const float*)d_in[5];  // [IS, H]
    const float* suw = (const float*)d_in[6];  // [IS, H]
    const float* sdw = (const float*)d_in[7];  // [H, IS]
    float* out = (float*)d_out;

    // 1. routing
    route_kernel<<<T_TOK * 32 / 256, 256>>>(x, gw);
    // 2. per-expert token lists (deterministic)
    build_kernel<<<NE, 256>>>();
    // 3. shared gate+up (M=2048, N=5632, K=2048) -> d_Hs
    swiglu_gemm_k<false><<<dim3(ISD / 64, T_TOK / 64, 1), 256>>>(x, sgw, suw, ISD, HD);
    // 4. routed gate+up gathered (N=1408, K=2048) -> d_Hr
    swiglu_gemm_k<true ><<<dim3(ID  / 64, T_TOK / 64, NE), 256>>>(x, egw, euw, ID, HD);
    // 5. shared down (M=2048, N=2048, K=5632) -> out (full overwrite)
    down_gemm_k<false><<<dim3(HD / 64, T_TOK / 64, 1), 256>>>(sdw, out, HD, ISD);
    // 6. routed down, weight folded (N=2048, K=1408) -> d_Y
    down_gemm_k<true ><<<dim3(HD / 64, T_TOK / 64, NE), 256>>>(edw, nullptr, HD, ID);
    // 7. combine
    combine_kernel<<<(T_TOK * HD / 4) / 256, 256>>>(out);
}

// round 2
// speedup vs baseline: 2.9350x; 2.9350x over previous
#include <cuda_runtime.h>
#include <math.h>

#define T_TOK 2048
#define NE 8
#define TOPK 2
#define HD 2048
#define ID 1408
#define ISD 5632

#define BM 128
#define BN 64
#define BK 16
#define SSTR 20   // smem row stride in floats (16 + 4 pad)

// ---------------- scratch (static device globals; no allocation) -------------
__device__ float d_Hs[(size_t)T_TOK * ISD];
__device__ float d_Hr[(size_t)NE * T_TOK * ID];
__device__ float d_Y [(size_t)NE * T_TOK * HD];
__device__ int   d_tok[NE * T_TOK];
__device__ float d_wt [NE * T_TOK];
__device__ int   d_cnt[NE];
__device__ int   d_slot[T_TOK * TOPK];
__device__ int   d_topki[T_TOK * TOPK];
__device__ float d_topkw[T_TOK * TOPK];

// ---------------- small PTX helpers ------------------------------------------
__device__ __forceinline__ unsigned smem_u32(const void* p) {
    return (unsigned)__cvta_generic_to_shared(p);
}
__device__ __forceinline__ void cp16(unsigned dst, const void* src) {
    asm volatile("cp.async.cg.shared.global [%0], [%1], 16;\n" :: "r"(dst), "l"(src));
}
__device__ __forceinline__ void cp_commit() { asm volatile("cp.async.commit_group;\n"); }
template <int N>
__device__ __forceinline__ void cp_wait() { asm volatile("cp.async.wait_group %0;\n" :: "n"(N)); }
__device__ __forceinline__ unsigned f2tf(float f) {
    unsigned r; asm("cvt.rna.tf32.f32 %0, %1;" : "=r"(r) : "f"(f)); return r;
}
__device__ __forceinline__ void mma1688(float c[4], const unsigned a[4], const unsigned b[2]) {
    asm volatile(
        "mma.sync.aligned.m16n8k8.row.col.f32.tf32.tf32.f32 "
        "{%0,%1,%2,%3},{%4,%5,%6,%7},{%8,%9},{%0,%1,%2,%3};\n"
        : "+f"(c[0]), "+f"(c[1]), "+f"(c[2]), "+f"(c[3])
        : "r"(a[0]), "r"(a[1]), "r"(a[2]), "r"(a[3]), "r"(b[0]), "r"(b[1]));
}

// ---------------- routing ----------------------------------------------------
__global__ void route_kernel(const float* __restrict__ x, const float* __restrict__ gw)
{
    int warp = (blockIdx.x * blockDim.x + threadIdx.x) >> 5;
    int lane = threadIdx.x & 31;
    if (warp >= T_TOK) return;
    const float* xr = x + (size_t)warp * HD;

    float s[NE];
#pragma unroll
    for (int e = 0; e < NE; e++) s[e] = 0.f;
    for (int k = lane; k < HD; k += 32) {
        float xv = xr[k];
#pragma unroll
        for (int e = 0; e < NE; e++) s[e] += xv * gw[e * HD + k];
    }
#pragma unroll
    for (int e = 0; e < NE; e++)
#pragma unroll
        for (int off = 16; off; off >>= 1)
            s[e] += __shfl_down_sync(0xffffffffu, s[e], off);

    if (lane == 0) {
        float mx = s[0];
#pragma unroll
        for (int e = 1; e < NE; e++) mx = fmaxf(mx, s[e]);
        float g[NE], sum = 0.f;
#pragma unroll
        for (int e = 0; e < NE; e++) { g[e] = expf(s[e] - mx); sum += g[e]; }
        float inv = 1.f / sum;
#pragma unroll
        for (int e = 0; e < NE; e++) g[e] *= inv;
        int i0 = 0; float v0 = g[0];
#pragma unroll
        for (int e = 1; e < NE; e++) if (g[e] > v0) { v0 = g[e]; i0 = e; }
        int i1 = -1; float v1 = -1.f;
#pragma unroll
        for (int e = 0; e < NE; e++) if (e != i0 && g[e] > v1) { v1 = g[e]; i1 = e; }
        float dn = 1.f / (v0 + v1);
        d_topki[warp * 2 + 0] = i0;  d_topkw[warp * 2 + 0] = v0 * dn;
        d_topki[warp * 2 + 1] = i1;  d_topkw[warp * 2 + 1] = v1 * dn;
    }
}

// ---------------- deterministic per-expert compaction -------------------------
__global__ void build_kernel()
{
    int e = blockIdx.x;
    int tid = threadIdx.x;
    int lane = tid & 31, w = tid >> 5;
    __shared__ int warp_sums[8];
    __shared__ int s_base;
    if (tid == 0) s_base = 0;
    __syncthreads();

    for (int c = 0; c < T_TOK; c += 256) {
        int t = c + tid;
        int k = -1;
        if (d_topki[2 * t] == e) k = 0;
        else if (d_topki[2 * t + 1] == e) k = 1;
        int flag = (k >= 0) ? 1 : 0;
        unsigned bal = __ballot_sync(0xffffffffu, flag);
        int pre = __popc(bal & ((1u << lane) - 1u));
        if (lane == 31) warp_sums[w] = pre + flag;
        __syncthreads();
        int wbase = 0;
        for (int i = 0; i < w; i++) wbase += warp_sums[i];
        int pos = s_base + wbase + pre;
        if (flag) {
            d_tok [e * T_TOK + pos] = t;
            d_wt  [e * T_TOK + pos] = d_topkw[2 * t + k];
            d_slot[2 * t + k]       = e * T_TOK + pos;
        }
        __syncthreads();
        if (tid == 0) {
            int tot = 0;
            for (int i = 0; i < 8; i++) tot += warp_sums[i];
            s_base += tot;
        }
        __syncthreads();
    }
    if (tid == 0) d_cnt[e] = s_base;
}

// ================= TF32 MMA fused gate+up with SiLU epilogue ==================
// C[m][n] = silu(A·Bg^T) * (A·Bu^T). A rows gathered when EXPERT.
template <bool EXPERT>
__global__ __launch_bounds__(256, 1)
void swiglu_mma_k(const float* __restrict__ A,
                  const float* __restrict__ Bg_all,
                  const float* __restrict__ Bu_all,
                  int N, int Kd)
{
    const int z = EXPERT ? blockIdx.z : 0;
    const float* Bg = Bg_all + (size_t)z * N * Kd;
    const float* Bu = Bu_all + (size_t)z * N * Kd;
    float* C = EXPERT ? (d_Hr + (size_t)z * T_TOK * N) : d_Hs;
    const int M = EXPERT ? d_cnt[z] : T_TOK;

    const int row0 = blockIdx.y * BM;
    if (row0 >= M) return;
    const int col0 = blockIdx.x * BN;

    __shared__ float As [2][BM * SSTR];
    __shared__ float Bgs[2][BN * SSTR];
    __shared__ float Bus[2][BN * SSTR];

    const int tid = threadIdx.x, lane = tid & 31, warp = tid >> 5;
    const int wm = warp >> 1, wn = warp & 1;
    const int gr = lane >> 2, gc = lane & 3;

    // global load assignment: each thread owns A rows (tid/4, 64+tid/4), k-chunk (tid&3)*4
    const int ar1 = tid >> 2, ar2 = 64 + (tid >> 2);
    const int kc  = (tid & 3) * 4;
    int r1 = row0 + ar1, r2 = row0 + ar2;
    int g1 = (r1 < M) ? (EXPERT ? d_tok[z * T_TOK + r1] : r1) : 0;
    int g2 = (r2 < M) ? (EXPERT ? d_tok[z * T_TOK + r2] : r2) : 0;
    const float* Ap1 = A + (size_t)g1 * Kd + kc;
    const float* Ap2 = A + (size_t)g2 * Kd + kc;
    const int br = tid >> 2;
    const float* Bgp = Bg + (size_t)(col0 + br) * Kd + kc;
    const float* Bup = Bu + (size_t)(col0 + br) * Kd + kc;

    unsigned sa1[2], sa2[2], sbg[2], sbu[2];
#pragma unroll
    for (int s = 0; s < 2; s++) {
        sa1[s] = smem_u32(&As [s][ar1 * SSTR + kc]);
        sa2[s] = smem_u32(&As [s][ar2 * SSTR + kc]);
        sbg[s] = smem_u32(&Bgs[s][br  * SSTR + kc]);
        sbu[s] = smem_u32(&Bus[s][br  * SSTR + kc]);
    }

    float accg[2][4][4] = {}, accu[2][4][4] = {};

    const int Kt = Kd / BK;
    // prefetch stage 0
    cp16(sa1[0], Ap1); cp16(sa2[0], Ap2);
    cp16(sbg[0], Bgp); cp16(sbu[0], Bup);
    cp_commit();

    for (int kt = 0; kt < Kt; kt++) {
        const int cur = kt & 1, nxt = cur ^ 1;
        if (kt + 1 < Kt) {
            const int ko = (kt + 1) * BK;
            cp16(sa1[nxt], Ap1 + ko); cp16(sa2[nxt], Ap2 + ko);
            cp16(sbg[nxt], Bgp + ko); cp16(sbu[nxt], Bup + ko);
            cp_commit();
            cp_wait<1>();
        } else {
            cp_wait<0>();
        }
        __syncthreads();

        const float* as = As [cur];
        const float* bgs = Bgs[cur];
        const float* bus = Bus[cur];
#pragma unroll
        for (int ks = 0; ks < 2; ks++) {
            const int k = ks * 8;
            unsigned afr[2][4];
#pragma unroll
            for (int mt = 0; mt < 2; mt++) {
                const int mb = wm * 32 + mt * 16;
                afr[mt][0] = f2tf(as[(mb + gr    ) * SSTR + k + gc    ]);
                afr[mt][1] = f2tf(as[(mb + gr + 8) * SSTR + k + gc    ]);
                afr[mt][2] = f2tf(as[(mb + gr    ) * SSTR + k + gc + 4]);
                afr[mt][3] = f2tf(as[(mb + gr + 8) * SSTR + k + gc + 4]);
            }
#pragma unroll
            for (int nt = 0; nt < 4; nt++) {
                const int nb = wn * 32 + nt * 8;
                unsigned bg[2], bu[2];
                bg[0] = f2tf(bgs[(nb + gr) * SSTR + k + gc    ]);
                bg[1] = f2tf(bgs[(nb + gr) * SSTR + k + gc + 4]);
                bu[0] = f2tf(bus[(nb + gr) * SSTR + k + gc    ]);
                bu[1] = f2tf(bus[(nb + gr) * SSTR + k + gc + 4]);
#pragma unroll
                for (int mt = 0; mt < 2; mt++) {
                    mma1688(accg[mt][nt], afr[mt], bg);
                    mma1688(accu[mt][nt], afr[mt], bu);
                }
            }
        }
        __syncthreads();
    }

    // epilogue: silu(g)*u
#pragma unroll
    for (int mt = 0; mt < 2; mt++) {
        const int mlo = row0 + wm * 32 + mt * 16 + gr;
        const int mhi = mlo + 8;
#pragma unroll
        for (int nt = 0; nt < 4; nt++) {
            const int n = col0 + wn * 32 + nt * 8 + gc * 2;
            if (mlo < M) {
                float g0 = accg[mt][nt][0], g1v = accg[mt][nt][1];
                float2 v;
                v.x = g0  / (1.f + expf(-g0 )) * accu[mt][nt][0];
                v.y = g1v / (1.f + expf(-g1v)) * accu[mt][nt][1];
                *(float2*)(C + (size_t)mlo * N + n) = v;
            }
            if (mhi < M) {
                float g2 = accg[mt][nt][2], g3 = accg[mt][nt][3];
                float2 v;
                v.x = g2 / (1.f + expf(-g2)) * accu[mt][nt][2];
                v.y = g3 / (1.f + expf(-g3)) * accu[mt][nt][3];
                *(float2*)(C + (size_t)mhi * N + n) = v;
            }
        }
    }
}

// ================= TF32 MMA down-projection ===================================
template <bool EXPERT>
__global__ __launch_bounds__(256, 1)
void down_mma_k(const float* __restrict__ B_all, float* __restrict__ Cout,
                int N, int Kd)
{
    const int z = EXPERT ? blockIdx.z : 0;
    const float* A = EXPERT ? (d_Hr + (size_t)z * T_TOK * Kd) : d_Hs;
    const float* B = B_all + (size_t)z * N * Kd;
    float* C = EXPERT ? (d_Y + (size_t)z * T_TOK * N) : Cout;
    const int M = EXPERT ? d_cnt[z] : T_TOK;

    const int row0 = blockIdx.y * BM;
    if (row0 >= M) return;
    const int col0 = blockIdx.x * BN;

    __shared__ float As[2][BM * SSTR];
    __shared__ float Bs[2][BN * SSTR];

    const int tid = threadIdx.x, lane = tid & 31, warp = tid >> 5;
    const int wm = warp >> 1, wn = warp & 1;
    const int gr = lane >> 2, gc = lane & 3;

    const int ar1 = tid >> 2, ar2 = 64 + (tid >> 2);
    const int kc  = (tid & 3) * 4;
    int r1 = row0 + ar1, r2 = row0 + ar2;
    const float* Ap1 = A + (size_t)((r1 < M) ? r1 : 0) * Kd + kc;
    const float* Ap2 = A + (size_t)((r2 < M) ? r2 : 0) * Kd + kc;
    const int br = tid >> 2;
    const float* Bp = B + (size_t)(col0 + br) * Kd + kc;

    unsigned sa1[2], sa2[2], sb[2];
#pragma unroll
    for (int s = 0; s < 2; s++) {
        sa1[s] = smem_u32(&As[s][ar1 * SSTR + kc]);
        sa2[s] = smem_u32(&As[s][ar2 * SSTR + kc]);
        sb [s] = smem_u32(&Bs[s][br  * SSTR + kc]);
    }

    float acc[2][4][4] = {};

    const int Kt = Kd / BK;
    cp16(sa1[0], Ap1); cp16(sa2[0], Ap2); cp16(sb[0], Bp);
    cp_commit();

    for (int kt = 0; kt < Kt; kt++) {
        const int cur = kt & 1, nxt = cur ^ 1;
        if (kt + 1 < Kt) {
            const int ko = (kt + 1) * BK;
            cp16(sa1[nxt], Ap1 + ko); cp16(sa2[nxt], Ap2 + ko); cp16(sb[nxt], Bp + ko);
            cp_commit();
            cp_wait<1>();
        } else {
            cp_wait<0>();
        }
        __syncthreads();

        const float* as = As[cur];
        const float* bs = Bs[cur];
#pragma unroll
        for (int ks = 0; ks < 2; ks++) {
            const int k = ks * 8;
            unsigned afr[2][4];
#pragma unroll
            for (int mt = 0; mt < 2; mt++) {
                const int mb = wm * 32 + mt * 16;
                afr[mt][0] = f2tf(as[(mb + gr    ) * SSTR + k + gc    ]);
                afr[mt][1] = f2tf(as[(mb + gr + 8) * SSTR + k + gc    ]);
                afr[mt][2] = f2tf(as[(mb + gr    ) * SSTR + k + gc + 4]);
                afr[mt][3] = f2tf(as[(mb + gr + 8) * SSTR + k + gc + 4]);
            }
#pragma unroll
            for (int nt = 0; nt < 4; nt++) {
                const int nb = wn * 32 + nt * 8;
                unsigned bf[2];
                bf[0] = f2tf(bs[(nb + gr) * SSTR + k + gc    ]);
                bf[1] = f2tf(bs[(nb + gr) * SSTR + k + gc + 4]);
#pragma unroll
                for (int mt = 0; mt < 2; mt++)
                    mma1688(acc[mt][nt], afr[mt], bf);
            }
        }
        __syncthreads();
    }

#pragma unroll
    for (int mt = 0; mt < 2; mt++) {
        const int mlo = row0 + wm * 32 + mt * 16 + gr;
        const int mhi = mlo + 8;
        float slo = 1.f, shi = 1.f;
        if (EXPERT) {
            if (mlo < M) slo = d_wt[z * T_TOK + mlo];
            if (mhi < M) shi = d_wt[z * T_TOK + mhi];
        }
#pragma unroll
        for (int nt = 0; nt < 4; nt++) {
            const int n = col0 + wn * 32 + nt * 8 + gc * 2;
            if (mlo < M)
                *(float2*)(C + (size_t)mlo * N + n) =
                    make_float2(acc[mt][nt][0] * slo, acc[mt][nt][1] * slo);
            if (mhi < M)
                *(float2*)(C + (size_t)mhi * N + n) =
                    make_float2(acc[mt][nt][2] * shi, acc[mt][nt][3] * shi);
        }
    }
}

// ---------------- final combine ----------------------------------------------
__global__ void combine_kernel(float* __restrict__ out)
{
    int idx = blockIdx.x * blockDim.x + threadIdx.x;
    int t  = idx / (HD / 4);
    int h4 = idx % (HD / 4);
    int s0 = d_slot[2 * t], s1 = d_slot[2 * t + 1];
    float4 o = ((float4*)out)[idx];
    float4 a = ((const float4*)(d_Y + (size_t)s0 * HD))[h4];
    float4 b = ((const float4*)(d_Y + (size_t)s1 * HD))[h4];
    o.x += a.x + b.x;  o.y += a.y + b.y;  o.z += a.z + b.z;  o.w += a.w + b.w;
    ((float4*)out)[idx] = o;
}

// ---------------- launcher ---------------------------------------------------
extern "C" void kernel_launch(void* const* d_in, const int* in_sizes, int n_in,
                              void* d_out, int out_size)
{
    const float* x   = (const float*)d_in[0];
    const float* gw  = (const float*)d_in[1];
    const float* egw = (const float*)d_in[2];
    const float* euw = (const float*)d_in[3];
    const float* edw = (const float*)d_in[4];
    const float* sgw = (const float*)d_in[5];
    const float* suw = (const float*)d_in[6];
    const float* sdw = (const float*)d_in[7];
    float* out = (float*)d_out;

    route_kernel<<<T_TOK * 32 / 256, 256>>>(x, gw);
    build_kernel<<<NE, 256>>>();
    // shared gate+up: M=2048, N=5632, K=2048
    swiglu_mma_k<false><<<dim3(ISD / BN, T_TOK / BM, 1), 256>>>(x, sgw, suw, ISD, HD);
    // routed gate+up (gathered): N=1408, K=2048
    swiglu_mma_k<true ><<<dim3(ID  / BN, T_TOK / BM, NE), 256>>>(x, egw, euw, ID, HD);
    // shared down: M=2048, N=2048, K=5632 -> out (full overwrite)
    down_mma_k<false><<<dim3(HD / BN, T_TOK / BM, 1), 256>>>(sdw, out, HD, ISD);
    // routed down (weight folded): N=2048, K=1408
    down_mma_k<true ><<<dim3(HD / BN, T_TOK / BM, NE), 256>>>(edw, nullptr, HD, ID);
    combine_kernel<<<(T_TOK * HD / 4) / 256, 256>>>(out);
}